// round 11
// baseline (speedup 1.0000x reference)
#include <cuda_runtime.h>
#include <cuda_bf16.h>
#include <math.h>

#define NBATCH 32
#define NNODE  512
#define NHEAD  8
#define FHID   16

// ---------------- scratch (device globals; no allocations) ----------------
__device__ float    g_hp1[NBATCH*NHEAD*NNODE*FHID];   // 8 MB
__device__ float    g_as [NBATCH*NHEAD*NNODE];
__device__ float    g_Es [NBATCH*NHEAD*NNODE];
__device__ float    g_Fs [NBATCH*NHEAD*NNODE];
__device__ float    g_ad [NBATCH*NHEAD*NNODE];
__device__ float    g_Ed [NBATCH*NHEAD*NNODE];
__device__ float    g_Fd [NBATCH*NHEAD*NNODE];
__device__ unsigned g_bits[NBATCH*NNODE*16];          // 1 MB bit-packed adjacency
__device__ float    g_x  [NBATCH*NNODE*128];          // 8 MB layer-2 input
__device__ float    g_hp2[NBATCH*NNODE*64];           // 4 MB
__device__ float    g_as2[NBATCH*NNODE];
__device__ float    g_ad2[NBATCH*NNODE];

// ---------------- packed f32x2 helpers (sm_103a) ----------------
static __device__ __forceinline__ unsigned long long pk2(float lo, float hi) {
    unsigned long long r;
    asm("mov.b64 %0,{%1,%2};" : "=l"(r) : "f"(lo), "f"(hi));
    return r;
}
static __device__ __forceinline__ void upk2(unsigned long long v, float& lo, float& hi) {
    asm("mov.b64 {%0,%1},%2;" : "=f"(lo), "=f"(hi) : "l"(v));
}
static __device__ __forceinline__ unsigned long long fma2(unsigned long long a,
                                                          unsigned long long b,
                                                          unsigned long long c) {
    unsigned long long d;
    asm("fma.rn.f32x2 %0,%1,%2,%3;" : "=l"(d) : "l"(a), "l"(b), "l"(c));
    return d;
}
static __device__ __forceinline__ unsigned long long add2(unsigned long long a,
                                                          unsigned long long b) {
    unsigned long long d;
    asm("add.rn.f32x2 %0,%1,%2;" : "=l"(d) : "l"(a), "l"(b));
    return d;
}

// ---------------- K0: bit-pack adjacency ----------------
__global__ void k_pack(const int* __restrict__ adj) {
    int idx = blockIdx.x * 256 + threadIdx.x;
    unsigned m = __ballot_sync(0xffffffffu, adj[idx] > 0);
    if ((threadIdx.x & 31) == 0) g_bits[idx >> 5] = m;
}

// ---------------- probe: keeps the ncu capture slot on k_fuse ----------------
__global__ void k_probe() {}

// ---------------- K1: layer-1 projection + tanh + exp tables ----------------
// grid (8, 2, 32), block 512; warp-per-node, lane owns output pair
__global__ void __launch_bounds__(512) k_proj1(
    const float* __restrict__ features, const float* __restrict__ line_emb,
    const int*   __restrict__ v_types,  const float* __restrict__ w1,
    const float* __restrict__ a_src1,   const float* __restrict__ a_dst1)
{
    extern __shared__ float sm1[];
    float* ws   = sm1;             // 12288: [t][f][l64]
    float* xv   = ws + 12288;      // 4096: 64 nodes x 64
    float* asr  = xv + 4096;       // 64
    float* ads  = asr + 64;        // 64
    int*   vt   = (int*)(ads + 64);// 64
    int tid = threadIdx.x;
    int bx = blockIdx.x, hh = blockIdx.y, b = blockIdx.z;
    int nbase = bx * 64;

    for (int i = tid; i < 12288; i += 512) {
        int l64 = i & 63, f = (i >> 6) & 63, t = i >> 12;
        int h = hh * 4 + (l64 >> 4), o = l64 & 15;
        ws[i] = w1[((t * 8 + h) * 64 + f) * 16 + o];
    }
    for (int i = tid; i < 4096; i += 512) {
        int node = i >> 6, f = i & 63;
        int n = nbase + node;
        xv[i] = (f < 32) ? features[(b * NNODE + n) * 32 + f]
                         : line_emb[(b * NNODE + n) * 32 + f - 32];
    }
    if (tid < 64) {
        int h = hh * 4 + (tid >> 4), o = tid & 15;
        asr[tid] = a_src1[h * 16 + o];
        ads[tid] = a_dst1[h * 16 + o];
        vt[tid] = v_types[b * NNODE + nbase + tid];
    }
    __syncthreads();

    int lane = tid & 31, w = tid >> 5;
    int gh = hh * 4 + (lane >> 3);
    float a0v = asr[2 * lane], a1v = asr[2 * lane + 1];
    float d0v = ads[2 * lane], d1v = ads[2 * lane + 1];
    unsigned long long z = pk2(0.f, 0.f);

    #pragma unroll
    for (int r = 0; r < 4; r++) {
        int nloc = w * 4 + r;
        int n = nbase + nloc;
        int ty = vt[nloc];
        const float* wp = ws + ty * 4096 + 2 * lane;
        const float* xp = xv + nloc * 64;
        unsigned long long acc0 = z, acc1 = z;
        #pragma unroll
        for (int f = 0; f < 64; f += 2) {
            float2 x2 = *(const float2*)&xp[f];
            unsigned long long w0 = *(const unsigned long long*)&wp[f * 64];
            unsigned long long w1v = *(const unsigned long long*)&wp[(f + 1) * 64];
            acc0 = fma2(pk2(x2.x, x2.x), w0, acc0);
            acc1 = fma2(pk2(x2.y, x2.y), w1v, acc1);
        }
        float v0, v1;
        upk2(add2(acc0, acc1), v0, v1);
        int o = (2 * lane) & 15;
        *(float2*)&g_hp1[((b * NHEAD + gh) * NNODE + n) * FHID + o] =
            make_float2(v0, v1);
        float th0 = tanhf(v0), th1 = tanhf(v1);
        float ps = th0 * a0v + th1 * a1v;
        float pd = th0 * d0v + th1 * d1v;
        #pragma unroll
        for (int off = 4; off; off >>= 1) {
            ps += __shfl_xor_sync(0xffffffffu, ps, off);
            pd += __shfl_xor_sync(0xffffffffu, pd, off);
        }
        if ((lane & 7) == 0) {
            int ai = (b * NHEAD + gh) * NNODE + n;
            g_as[ai] = ps; g_Es[ai] = expf(ps); g_Fs[ai] = expf(0.2f * ps);
            g_ad[ai] = pd; g_Ed[ai] = expf(pd); g_Fd[ai] = expf(0.2f * pd);
        }
    }
}

// ---------------- K2: FUSED attn softmax + attn1 store + out1 GEMM + elu ----------------
// grid (2, 8, 32), 256 threads (1 row/thread), dyn smem 57408 B; 3 blocks/SM
// hp loads vectorized: 4x LDS.128 per element (was 8x LDS.64)
__global__ void __launch_bounds__(256) k_fuse(const float* __restrict__ b1,
                                              float* __restrict__ attn_out) {
    extern __shared__ float smf[];
    float*    hp_s   = smf;                       // 8192 floats [m][o]
    float4*   tbl    = (float4*)(smf + 8192);     // 512 float4 (ad, Ed, Fd, 0)
    unsigned* bits_s = (unsigned*)(smf + 10240);  // 4096 words, layout [w][r]
    float*    b1s    = smf + 14336;               // 16
    int tid = threadIdx.x;
    int nh = blockIdx.x, h = blockIdx.y, b = blockIdx.z;
    int bh = b * NHEAD + h;
    int n0 = nh * 256;

    for (int i = tid; i < 8192; i += 256) hp_s[i] = g_hp1[bh * 8192 + i];
    for (int i = tid; i < 512; i += 256)
        tbl[i] = make_float4(g_ad[bh * 512 + i], g_Ed[bh * 512 + i],
                             g_Fd[bh * 512 + i], 0.f);
    for (int i = tid; i < 4096; i += 256) {
        int w = i >> 8, r = i & 255;
        bits_s[i] = g_bits[b * 8192 + (n0 + r) * 16 + w];
    }
    if (tid < 16) b1s[tid] = b1[tid];

    int na = n0 + tid;
    float as_a = g_as[bh * 512 + na];
    float Es_a = g_Es[bh * 512 + na], Fs_a = g_Fs[bh * 512 + na];
    __syncthreads();

    // pass A: row sum (no shuffles, no barriers)
    float SEa = 0.f, SFa = 0.f;
    for (int mw = 0; mw < 16; mw++) {
        unsigned wa = bits_s[mw * 256 + tid];
        #pragma unroll
        for (int mi = 0; mi < 32; mi++) {
            float4 t = tbl[mw * 32 + mi];
            float sa = as_a + t.x;
            bool ba = (wa >> mi) & 1u;
            SEa += (ba && sa >= 0.f) ? t.y : 0.f;
            SFa += (ba && sa <  0.f) ? t.z : 0.f;
        }
    }
    float inva = 1.f / fmaf(Es_a, SEa, Fs_a * SFa);
    float Esa = Es_a * inva, Fsa = Fs_a * inva;

    // pass B: attn recompute + store + fma2 GEMM (hp via LDS.128)
    unsigned long long acc[8];
    unsigned long long z = pk2(0.f, 0.f);
    #pragma unroll
    for (int q = 0; q < 8; q++) acc[q] = z;

    float* rowa = attn_out + (size_t)bh * 512 * 512 + (size_t)na * 512;
    for (int mw = 0; mw < 16; mw++) {
        unsigned wa = bits_s[mw * 256 + tid];
        #pragma unroll
        for (int half = 0; half < 2; half++) {
            float ea16[16];
            #pragma unroll
            for (int ci = 0; ci < 16; ci++) {
                int mi = half * 16 + ci;
                int m = mw * 32 + mi;
                float4 t = tbl[m];
                float sa = as_a + t.x;
                float ca = (sa >= 0.f) ? Esa : Fsa;
                if (!((wa >> mi) & 1u)) ca = 0.f;
                float ea = ca * ((sa >= 0.f) ? t.y : t.z);
                ea16[ci] = ea;
                unsigned long long pa = pk2(ea, ea);
                const ulonglong2* hq2 = (const ulonglong2*)(hp_s + m * 16);
                ulonglong2 h0 = hq2[0];
                ulonglong2 h1 = hq2[1];
                ulonglong2 h2 = hq2[2];
                ulonglong2 h3 = hq2[3];
                acc[0] = fma2(pa, h0.x, acc[0]);
                acc[1] = fma2(pa, h0.y, acc[1]);
                acc[2] = fma2(pa, h1.x, acc[2]);
                acc[3] = fma2(pa, h1.y, acc[3]);
                acc[4] = fma2(pa, h2.x, acc[4]);
                acc[5] = fma2(pa, h2.y, acc[5]);
                acc[6] = fma2(pa, h3.x, acc[6]);
                acc[7] = fma2(pa, h3.y, acc[7]);
            }
            float4* oa = (float4*)(rowa + mw * 32 + half * 16);
            __stcs(oa + 0, make_float4(ea16[0],  ea16[1],  ea16[2],  ea16[3]));
            __stcs(oa + 1, make_float4(ea16[4],  ea16[5],  ea16[6],  ea16[7]));
            __stcs(oa + 2, make_float4(ea16[8],  ea16[9],  ea16[10], ea16[11]));
            __stcs(oa + 3, make_float4(ea16[12], ea16[13], ea16[14], ea16[15]));
        }
    }

    // epilogue: +b1, elu, scatter to g_x
    float va[16];
    #pragma unroll
    for (int q = 0; q < 8; q++)
        upk2(acc[q], va[2 * q], va[2 * q + 1]);
    float ra[16];
    #pragma unroll
    for (int k = 0; k < 16; k++) {
        float xa = va[k] + b1s[k];
        ra[k] = xa > 0.f ? xa : expm1f(xa);
    }
    float* da = &g_x[(size_t)(b * 512 + na) * 128 + h * 16];
    #pragma unroll
    for (int q = 0; q < 4; q++)
        ((float4*)da)[q] = make_float4(ra[4*q], ra[4*q+1], ra[4*q+2], ra[4*q+3]);
}

// ---------------- K3: layer-2 projection; LDG.128 weights, quad-per-lane ----------------
// grid (16, 32), block 256 (8 warps); half-warp per node, lane owns output quad
__global__ void __launch_bounds__(256, 2) k_proj2(
    const int* __restrict__ v_types, const float* __restrict__ w2,
    const float* __restrict__ a_src2, const float* __restrict__ a_dst2)
{
    __shared__ float xv[32 * 128];
    __shared__ float asw[64], adw[64];
    __shared__ int   vt[32];
    int tid = threadIdx.x, b = blockIdx.y, bx = blockIdx.x;
    int nbase = bx * 32;

    for (int i = tid; i < 4096; i += 256)
        xv[i] = g_x[(size_t)(b * 512 + nbase) * 128 + i];
    if (tid < 64) { asw[tid] = a_src2[tid]; adw[tid] = a_dst2[tid]; }
    if (tid < 32) vt[tid] = v_types[b * 512 + nbase + tid];
    __syncthreads();

    int lane = tid & 31, w = tid >> 5;
    int half = lane >> 4, l16 = lane & 15;
    int o = l16 * 4;
    float a0v = asw[o], a1v = asw[o + 1], a2v = asw[o + 2], a3v = asw[o + 3];
    float d0v = adw[o], d1v = adw[o + 1], d2v = adw[o + 2], d3v = adw[o + 3];
    unsigned long long z = pk2(0.f, 0.f);

    #pragma unroll
    for (int pass = 0; pass < 2; pass++) {
        int nloc = pass * 16 + w * 2 + half;
        int n = nbase + nloc;
        int ty = vt[nloc];
        const float4* wp = (const float4*)(w2 + ty * 8192 + o);
        const float* xp = xv + nloc * 128;
        unsigned long long acc01 = z, acc23 = z;
        #pragma unroll
        for (int c = 0; c < 16; c++) {
            float4 wb[8];
            #pragma unroll
            for (int j = 0; j < 8; j++)
                wb[j] = __ldg(wp + (c * 8 + j) * 16);
            float4 xa = *(const float4*)&xp[c * 8];
            float4 xc = *(const float4*)&xp[c * 8 + 4];
            float xs[8] = {xa.x, xa.y, xa.z, xa.w, xc.x, xc.y, xc.z, xc.w};
            #pragma unroll
            for (int j = 0; j < 8; j++) {
                unsigned long long xx = pk2(xs[j], xs[j]);
                acc01 = fma2(xx, pk2(wb[j].x, wb[j].y), acc01);
                acc23 = fma2(xx, pk2(wb[j].z, wb[j].w), acc23);
            }
        }
        float v0, v1, v2, v3;
        upk2(acc01, v0, v1);
        upk2(acc23, v2, v3);
        *(float4*)&g_hp2[(size_t)(b * 512 + n) * 64 + o] =
            make_float4(v0, v1, v2, v3);
        float th0 = tanhf(v0), th1 = tanhf(v1), th2 = tanhf(v2), th3 = tanhf(v3);
        float ps = th0 * a0v + th1 * a1v + th2 * a2v + th3 * a3v;
        float pd = th0 * d0v + th1 * d1v + th2 * d2v + th3 * d3v;
        #pragma unroll
        for (int off = 8; off; off >>= 1) {
            ps += __shfl_xor_sync(0xffffffffu, ps, off);
            pd += __shfl_xor_sync(0xffffffffu, pd, off);
        }
        if (l16 == 0) {
            g_as2[b * 512 + n] = ps;
            g_ad2[b * 512 + n] = pd;
        }
    }
}

// ---------------- K4: layer-2 rows 0/1 + MLP + log_softmax ----------------
__global__ void __launch_bounds__(512) k_final(
    const float* __restrict__ b2,
    const float* __restrict__ fc1_w, const float* __restrict__ fc1_b,
    const float* __restrict__ fc2_w, const float* __restrict__ fc2_b,
    const float* __restrict__ fc3_w, const float* __restrict__ fc3_b,
    float* __restrict__ out_scores, float* __restrict__ out_vsm)
{
    __shared__ float att2[2 * 512];
    __shared__ float inv[2];
    __shared__ float part[512];
    __shared__ float xrow[128];
    __shared__ float vsm[64], v1[192], v2s[64];
    __shared__ float red[32];
    __shared__ float sc[2];
    int tid = threadIdx.x, b = blockIdx.x;
    int lane = tid & 31, wid = tid >> 5;

    float ad2 = g_ad2[b * 512 + tid];
    unsigned wrd  = g_bits[b * 8192 + (tid >> 5)];
    unsigned wrd1 = g_bits[b * 8192 + 16 + (tid >> 5)];
    float as0 = g_as2[b * 512 + 0], as1 = g_as2[b * 512 + 1];
    float s0 = as0 + ad2, s1 = as1 + ad2;
    float e0 = ((wrd  >> lane) & 1u) ? expf(s0 >= 0.f ? s0 : 0.2f * s0) : 0.f;
    float e1 = ((wrd1 >> lane) & 1u) ? expf(s1 >= 0.f ? s1 : 0.2f * s1) : 0.f;
    att2[tid] = e0;
    att2[512 + tid] = e1;
    float p0 = e0, p1 = e1;
    #pragma unroll
    for (int off = 16; off; off >>= 1) {
        p0 += __shfl_xor_sync(0xffffffffu, p0, off);
        p1 += __shfl_xor_sync(0xffffffffu, p1, off);
    }
    if (lane == 0) { red[wid] = p0; red[16 + wid] = p1; }
    __syncthreads();
    if (tid < 32) {
        float v = red[tid];
        #pragma unroll
        for (int off = 8; off; off >>= 1)
            v += __shfl_xor_sync(0xffffffffu, v, off);
        if (tid == 0)  inv[0] = 1.f / v;
        if (tid == 16) inv[1] = 1.f / v;
    }
    __syncthreads();

    {
        int r = tid >> 8, o = tid & 63, sub = (tid >> 6) & 3;
        const float* hp = g_hp2 + (size_t)b * 32768 + o;
        const float* av = att2 + r * 512 + sub * 128;
        float a0 = 0.f, a1 = 0.f, a2 = 0.f, a3 = 0.f;
        int mb = sub * 128;
        #pragma unroll 4
        for (int k = 0; k < 128; k += 4) {
            a0 = fmaf(av[k],     hp[(size_t)(mb + k) * 64],     a0);
            a1 = fmaf(av[k + 1], hp[(size_t)(mb + k + 1) * 64], a1);
            a2 = fmaf(av[k + 2], hp[(size_t)(mb + k + 2) * 64], a2);
            a3 = fmaf(av[k + 3], hp[(size_t)(mb + k + 3) * 64], a3);
        }
        part[tid] = (a0 + a1) + (a2 + a3);
    }
    __syncthreads();
    if (tid < 128) {
        int r = tid >> 6, o = tid & 63;
        float x = (part[r * 256 + o] + part[r * 256 + 64 + o] +
                   part[r * 256 + 128 + o] + part[r * 256 + 192 + o]) * inv[r] + b2[o];
        xrow[tid] = x > 0.f ? x : expm1f(x);
    }
    __syncthreads();
    if (tid < 64) {
        float vv = xrow[tid] * xrow[64 + tid];
        vsm[tid] = vv;
        out_vsm[b * 64 + tid] = vv;
    }
    __syncthreads();
    if (tid < 192) {
        float acc = fc1_b[tid];
        for (int f = 0; f < 64; f++) acc = fmaf(vsm[f], fc1_w[f * 192 + tid], acc);
        v1[tid] = fmaxf(acc, 0.f);
    }
    __syncthreads();
    if (tid < 64) {
        float acc = fc2_b[tid];
        for (int f = 0; f < 192; f++) acc = fmaf(v1[f], fc2_w[f * 64 + tid], acc);
        v2s[tid] = fmaxf(acc, 0.f);
    }
    __syncthreads();
    if (tid < 2) {
        float acc = fc3_b[tid];
        for (int f = 0; f < 64; f++) acc = fmaf(v2s[f], fc3_w[f * 2 + tid], acc);
        sc[tid] = acc;
    }
    __syncthreads();
    if (tid < 2) {
        float m = fmaxf(sc[0], sc[1]);
        float lse = m + logf(expf(sc[0] - m) + expf(sc[1] - m));
        out_scores[b * 2 + tid] = sc[tid] - lse;
    }
}

// ---------------- launch ----------------
extern "C" void kernel_launch(void* const* d_in, const int* in_sizes, int n_in,
                              void* d_out, int out_size) {
    (void)in_sizes; (void)n_in; (void)out_size;
    const float* features = (const float*)d_in[0];
    const int*   adj      = (const int*)  d_in[1];
    const float* line_emb = (const float*)d_in[5];
    const int*   v_types  = (const int*)  d_in[6];
    const float* w1       = (const float*)d_in[7];
    const float* a_src1   = (const float*)d_in[8];
    const float* a_dst1   = (const float*)d_in[9];
    const float* b1       = (const float*)d_in[10];
    const float* w2       = (const float*)d_in[11];
    const float* a_src2   = (const float*)d_in[12];
    const float* a_dst2   = (const float*)d_in[13];
    const float* b2       = (const float*)d_in[14];
    const float* fc1_w    = (const float*)d_in[15];
    const float* fc1_b    = (const float*)d_in[16];
    const float* fc2_w    = (const float*)d_in[17];
    const float* fc2_b    = (const float*)d_in[18];
    const float* fc3_w    = (const float*)d_in[19];
    const float* fc3_b    = (const float*)d_in[20];

    float* out   = (float*)d_out;
    float* vsm   = out + 64;       // v_sim_mul [32,64]
    float* attn1 = out + 2112;     // attn1 [32,8,512,512]

    cudaFuncSetAttribute(k_proj1, cudaFuncAttributeMaxDynamicSharedMemorySize, 67000);
    cudaFuncSetAttribute(k_fuse,  cudaFuncAttributeMaxDynamicSharedMemorySize, 58000);

    k_pack <<<32768, 256>>>(adj);
    k_proj1<<<dim3(8, 2, 32), 512, 66304>>>(features, line_emb, v_types, w1, a_src1, a_dst1);
    k_probe<<<1, 32>>>();
    k_fuse <<<dim3(2, 8, 32), 256, 57408>>>(b1, attn1);
    k_proj2<<<dim3(16, 32), 256>>>(v_types, w2, a_src2, a_dst2);
    k_final<<<32, 512>>>(b2, fc1_w, fc1_b, fc2_w, fc2_b, fc3_w, fc3_b, out, vsm);
}

// round 12
// speedup vs baseline: 1.0164x; 1.0164x over previous
#include <cuda_runtime.h>
#include <cuda_bf16.h>
#include <math.h>

#define NBATCH 32
#define NNODE  512
#define NHEAD  8
#define FHID   16

// ---------------- scratch (device globals; no allocations) ----------------
__device__ float    g_hp1[NBATCH*NHEAD*NNODE*FHID];   // 8 MB
__device__ float    g_as [NBATCH*NHEAD*NNODE];
__device__ float    g_Es [NBATCH*NHEAD*NNODE];
__device__ float    g_Fs [NBATCH*NHEAD*NNODE];
__device__ float    g_ad [NBATCH*NHEAD*NNODE];
__device__ float    g_Ed [NBATCH*NHEAD*NNODE];
__device__ float    g_Fd [NBATCH*NHEAD*NNODE];
__device__ unsigned g_bits[NBATCH*NNODE*16];          // 1 MB bit-packed adjacency
__device__ float    g_x  [NBATCH*NNODE*128];          // 8 MB layer-2 input
__device__ float    g_hp2[NBATCH*NNODE*64];           // 4 MB
__device__ float    g_as2[NBATCH*NNODE];
__device__ float    g_ad2[NBATCH*NNODE];

// ---------------- packed f32x2 helpers (sm_103a) ----------------
static __device__ __forceinline__ unsigned long long pk2(float lo, float hi) {
    unsigned long long r;
    asm("mov.b64 %0,{%1,%2};" : "=l"(r) : "f"(lo), "f"(hi));
    return r;
}
static __device__ __forceinline__ void upk2(unsigned long long v, float& lo, float& hi) {
    asm("mov.b64 {%0,%1},%2;" : "=f"(lo), "=f"(hi) : "l"(v));
}
static __device__ __forceinline__ unsigned long long fma2(unsigned long long a,
                                                          unsigned long long b,
                                                          unsigned long long c) {
    unsigned long long d;
    asm("fma.rn.f32x2 %0,%1,%2,%3;" : "=l"(d) : "l"(a), "l"(b), "l"(c));
    return d;
}
static __device__ __forceinline__ unsigned long long add2(unsigned long long a,
                                                          unsigned long long b) {
    unsigned long long d;
    asm("add.rn.f32x2 %0,%1,%2;" : "=l"(d) : "l"(a), "l"(b));
    return d;
}

// ---------------- K0: bit-pack adjacency ----------------
__global__ void k_pack(const int* __restrict__ adj) {
    int idx = blockIdx.x * 256 + threadIdx.x;
    unsigned m = __ballot_sync(0xffffffffu, adj[idx] > 0);
    if ((threadIdx.x & 31) == 0) g_bits[idx >> 5] = m;
}

// ---------------- probe: keeps the ncu capture slot on k_fuse ----------------
__global__ void k_probe() {}

// ---------------- K1: layer-1 projection + tanh + exp tables ----------------
// grid (8, 2, 32), block 512; warp-per-node, lane owns output pair
__global__ void __launch_bounds__(512) k_proj1(
    const float* __restrict__ features, const float* __restrict__ line_emb,
    const int*   __restrict__ v_types,  const float* __restrict__ w1,
    const float* __restrict__ a_src1,   const float* __restrict__ a_dst1)
{
    extern __shared__ float sm1[];
    float* ws   = sm1;             // 12288: [t][f][l64]
    float* xv   = ws + 12288;      // 4096: 64 nodes x 64
    float* asr  = xv + 4096;       // 64
    float* ads  = asr + 64;        // 64
    int*   vt   = (int*)(ads + 64);// 64
    int tid = threadIdx.x;
    int bx = blockIdx.x, hh = blockIdx.y, b = blockIdx.z;
    int nbase = bx * 64;

    for (int i = tid; i < 12288; i += 512) {
        int l64 = i & 63, f = (i >> 6) & 63, t = i >> 12;
        int h = hh * 4 + (l64 >> 4), o = l64 & 15;
        ws[i] = w1[((t * 8 + h) * 64 + f) * 16 + o];
    }
    for (int i = tid; i < 4096; i += 512) {
        int node = i >> 6, f = i & 63;
        int n = nbase + node;
        xv[i] = (f < 32) ? features[(b * NNODE + n) * 32 + f]
                         : line_emb[(b * NNODE + n) * 32 + f - 32];
    }
    if (tid < 64) {
        int h = hh * 4 + (tid >> 4), o = tid & 15;
        asr[tid] = a_src1[h * 16 + o];
        ads[tid] = a_dst1[h * 16 + o];
        vt[tid] = v_types[b * NNODE + nbase + tid];
    }
    __syncthreads();

    int lane = tid & 31, w = tid >> 5;
    int gh = hh * 4 + (lane >> 3);
    float a0v = asr[2 * lane], a1v = asr[2 * lane + 1];
    float d0v = ads[2 * lane], d1v = ads[2 * lane + 1];
    unsigned long long z = pk2(0.f, 0.f);

    #pragma unroll
    for (int r = 0; r < 4; r++) {
        int nloc = w * 4 + r;
        int n = nbase + nloc;
        int ty = vt[nloc];
        const float* wp = ws + ty * 4096 + 2 * lane;
        const float* xp = xv + nloc * 64;
        unsigned long long acc0 = z, acc1 = z;
        #pragma unroll
        for (int f = 0; f < 64; f += 2) {
            float2 x2 = *(const float2*)&xp[f];
            unsigned long long w0 = *(const unsigned long long*)&wp[f * 64];
            unsigned long long w1v = *(const unsigned long long*)&wp[(f + 1) * 64];
            acc0 = fma2(pk2(x2.x, x2.x), w0, acc0);
            acc1 = fma2(pk2(x2.y, x2.y), w1v, acc1);
        }
        float v0, v1;
        upk2(add2(acc0, acc1), v0, v1);
        int o = (2 * lane) & 15;
        *(float2*)&g_hp1[((b * NHEAD + gh) * NNODE + n) * FHID + o] =
            make_float2(v0, v1);
        float th0 = tanhf(v0), th1 = tanhf(v1);
        float ps = th0 * a0v + th1 * a1v;
        float pd = th0 * d0v + th1 * d1v;
        #pragma unroll
        for (int off = 4; off; off >>= 1) {
            ps += __shfl_xor_sync(0xffffffffu, ps, off);
            pd += __shfl_xor_sync(0xffffffffu, pd, off);
        }
        if ((lane & 7) == 0) {
            int ai = (b * NHEAD + gh) * NNODE + n;
            g_as[ai] = ps; g_Es[ai] = expf(ps); g_Fs[ai] = expf(0.2f * ps);
            g_ad[ai] = pd; g_Ed[ai] = expf(pd); g_Fd[ai] = expf(0.2f * pd);
        }
    }
}

// ---------------- K2: FUSED attn softmax + attn1 store + out1 GEMM + elu ----------------
// grid (4, 8, 32) = (nquarter, h, b), 256 threads; thread = (row 0..127, out-half)
// dyn smem 49216 B -> 4 blocks/SM = 32 warps. Inner math = proven R10 select+LDS.64 form.
__global__ void __launch_bounds__(256, 4) k_fuse(const float* __restrict__ b1,
                                                 float* __restrict__ attn_out) {
    extern __shared__ float smf[];
    float*    hp_s   = smf;                       // 8192 floats [m][o]
    float4*   tbl    = (float4*)(smf + 8192);     // 512 float4 (ad, Ed, Fd, 0)
    unsigned* bits_s = (unsigned*)(smf + 10240);  // 2048 words, layout [w][r], 128 rows
    float*    b1s    = smf + 12288;               // 16
    int tid = threadIdx.x;
    int nh = blockIdx.x, h = blockIdx.y, b = blockIdx.z;
    int bh = b * NHEAD + h;
    int n0 = nh * 128;

    for (int i = tid; i < 8192; i += 256) hp_s[i] = g_hp1[bh * 8192 + i];
    for (int i = tid; i < 512; i += 256)
        tbl[i] = make_float4(g_ad[bh * 512 + i], g_Ed[bh * 512 + i],
                             g_Fd[bh * 512 + i], 0.f);
    for (int i = tid; i < 2048; i += 256) {
        int w = i >> 7, r = i & 127;
        bits_s[i] = g_bits[b * 8192 + (n0 + r) * 16 + w];
    }
    if (tid < 16) b1s[tid] = b1[tid];

    int row = tid & 127;           // local row
    int half = tid >> 7;           // output half: columns half*8 .. half*8+7
    int na = n0 + row;
    float as_a = g_as[bh * 512 + na];
    float Es_a = g_Es[bh * 512 + na], Fs_a = g_Fs[bh * 512 + na];
    __syncthreads();

    // pass A: row sum (duplicated across the two half-threads; no shuffles/barriers)
    float SEa = 0.f, SFa = 0.f;
    for (int mw = 0; mw < 16; mw++) {
        unsigned wa = bits_s[mw * 128 + row];
        #pragma unroll
        for (int mi = 0; mi < 32; mi++) {
            float4 t = tbl[mw * 32 + mi];
            float sa = as_a + t.x;
            bool ba = (wa >> mi) & 1u;
            SEa += (ba && sa >= 0.f) ? t.y : 0.f;
            SFa += (ba && sa <  0.f) ? t.z : 0.f;
        }
    }
    float inva = 1.f / fmaf(Es_a, SEa, Fs_a * SFa);
    float Esa = Es_a * inva, Fsa = Fs_a * inva;

    // pass B: attn recompute + split store + fma2 GEMM over 8 owned outputs
    unsigned long long acc[4];
    unsigned long long z = pk2(0.f, 0.f);
    #pragma unroll
    for (int q = 0; q < 4; q++) acc[q] = z;

    float* rowa = attn_out + (size_t)bh * 512 * 512 + (size_t)na * 512;
    int hoff = half * 8;
    for (int mw = 0; mw < 16; mw++) {
        unsigned wa = bits_s[mw * 128 + row];
        #pragma unroll
        for (int hl = 0; hl < 2; hl++) {
            float ea16[16];
            #pragma unroll
            for (int ci = 0; ci < 16; ci++) {
                int mi = hl * 16 + ci;
                int m = mw * 32 + mi;
                float4 t = tbl[m];
                float sa = as_a + t.x;
                float ca = (sa >= 0.f) ? Esa : Fsa;
                if (!((wa >> mi) & 1u)) ca = 0.f;
                float ea = ca * ((sa >= 0.f) ? t.y : t.z);
                ea16[ci] = ea;
                unsigned long long pa = pk2(ea, ea);
                const unsigned long long* hq =
                    (const unsigned long long*)(hp_s + m * 16 + hoff);
                acc[0] = fma2(pa, hq[0], acc[0]);
                acc[1] = fma2(pa, hq[1], acc[1]);
                acc[2] = fma2(pa, hq[2], acc[2]);
                acc[3] = fma2(pa, hq[3], acc[3]);
            }
            if (hl == half) {
                float4* oa = (float4*)(rowa + mw * 32 + hl * 16);
                __stcs(oa + 0, make_float4(ea16[0],  ea16[1],  ea16[2],  ea16[3]));
                __stcs(oa + 1, make_float4(ea16[4],  ea16[5],  ea16[6],  ea16[7]));
                __stcs(oa + 2, make_float4(ea16[8],  ea16[9],  ea16[10], ea16[11]));
                __stcs(oa + 3, make_float4(ea16[12], ea16[13], ea16[14], ea16[15]));
            }
        }
    }

    // epilogue: +b1, elu, scatter 8 outputs to g_x
    float va[8];
    #pragma unroll
    for (int q = 0; q < 4; q++)
        upk2(acc[q], va[2 * q], va[2 * q + 1]);
    float ra[8];
    #pragma unroll
    for (int k = 0; k < 8; k++) {
        float xa = va[k] + b1s[hoff + k];
        ra[k] = xa > 0.f ? xa : expm1f(xa);
    }
    float* da = &g_x[(size_t)(b * 512 + na) * 128 + h * 16 + hoff];
    ((float4*)da)[0] = make_float4(ra[0], ra[1], ra[2], ra[3]);
    ((float4*)da)[1] = make_float4(ra[4], ra[5], ra[6], ra[7]);
}

// ---------------- K3: layer-2 projection; LDG.128 weights, quad-per-lane ----------------
// grid (16, 32), block 256 (8 warps); half-warp per node, lane owns output quad
__global__ void __launch_bounds__(256, 2) k_proj2(
    const int* __restrict__ v_types, const float* __restrict__ w2,
    const float* __restrict__ a_src2, const float* __restrict__ a_dst2)
{
    __shared__ float xv[32 * 128];
    __shared__ float asw[64], adw[64];
    __shared__ int   vt[32];
    int tid = threadIdx.x, b = blockIdx.y, bx = blockIdx.x;
    int nbase = bx * 32;

    for (int i = tid; i < 4096; i += 256)
        xv[i] = g_x[(size_t)(b * 512 + nbase) * 128 + i];
    if (tid < 64) { asw[tid] = a_src2[tid]; adw[tid] = a_dst2[tid]; }
    if (tid < 32) vt[tid] = v_types[b * 512 + nbase + tid];
    __syncthreads();

    int lane = tid & 31, w = tid >> 5;
    int half = lane >> 4, l16 = lane & 15;
    int o = l16 * 4;
    float a0v = asw[o], a1v = asw[o + 1], a2v = asw[o + 2], a3v = asw[o + 3];
    float d0v = adw[o], d1v = adw[o + 1], d2v = adw[o + 2], d3v = adw[o + 3];
    unsigned long long z = pk2(0.f, 0.f);

    #pragma unroll
    for (int pass = 0; pass < 2; pass++) {
        int nloc = pass * 16 + w * 2 + half;
        int n = nbase + nloc;
        int ty = vt[nloc];
        const float4* wp = (const float4*)(w2 + ty * 8192 + o);
        const float* xp = xv + nloc * 128;
        unsigned long long acc01 = z, acc23 = z;
        #pragma unroll
        for (int c = 0; c < 16; c++) {
            float4 wb[8];
            #pragma unroll
            for (int j = 0; j < 8; j++)
                wb[j] = __ldg(wp + (c * 8 + j) * 16);
            float4 xa = *(const float4*)&xp[c * 8];
            float4 xc = *(const float4*)&xp[c * 8 + 4];
            float xs[8] = {xa.x, xa.y, xa.z, xa.w, xc.x, xc.y, xc.z, xc.w};
            #pragma unroll
            for (int j = 0; j < 8; j++) {
                unsigned long long xx = pk2(xs[j], xs[j]);
                acc01 = fma2(xx, pk2(wb[j].x, wb[j].y), acc01);
                acc23 = fma2(xx, pk2(wb[j].z, wb[j].w), acc23);
            }
        }
        float v0, v1, v2, v3;
        upk2(acc01, v0, v1);
        upk2(acc23, v2, v3);
        *(float4*)&g_hp2[(size_t)(b * 512 + n) * 64 + o] =
            make_float4(v0, v1, v2, v3);
        float th0 = tanhf(v0), th1 = tanhf(v1), th2 = tanhf(v2), th3 = tanhf(v3);
        float ps = th0 * a0v + th1 * a1v + th2 * a2v + th3 * a3v;
        float pd = th0 * d0v + th1 * d1v + th2 * d2v + th3 * d3v;
        #pragma unroll
        for (int off = 8; off; off >>= 1) {
            ps += __shfl_xor_sync(0xffffffffu, ps, off);
            pd += __shfl_xor_sync(0xffffffffu, pd, off);
        }
        if (l16 == 0) {
            g_as2[b * 512 + n] = ps;
            g_ad2[b * 512 + n] = pd;
        }
    }
}

// ---------------- K4: layer-2 rows 0/1 + MLP + log_softmax ----------------
__global__ void __launch_bounds__(512) k_final(
    const float* __restrict__ b2,
    const float* __restrict__ fc1_w, const float* __restrict__ fc1_b,
    const float* __restrict__ fc2_w, const float* __restrict__ fc2_b,
    const float* __restrict__ fc3_w, const float* __restrict__ fc3_b,
    float* __restrict__ out_scores, float* __restrict__ out_vsm)
{
    __shared__ float att2[2 * 512];
    __shared__ float inv[2];
    __shared__ float part[512];
    __shared__ float xrow[128];
    __shared__ float vsm[64], v1[192], v2s[64];
    __shared__ float red[32];
    __shared__ float sc[2];
    int tid = threadIdx.x, b = blockIdx.x;
    int lane = tid & 31, wid = tid >> 5;

    float ad2 = g_ad2[b * 512 + tid];
    unsigned wrd  = g_bits[b * 8192 + (tid >> 5)];
    unsigned wrd1 = g_bits[b * 8192 + 16 + (tid >> 5)];
    float as0 = g_as2[b * 512 + 0], as1 = g_as2[b * 512 + 1];
    float s0 = as0 + ad2, s1 = as1 + ad2;
    float e0 = ((wrd  >> lane) & 1u) ? expf(s0 >= 0.f ? s0 : 0.2f * s0) : 0.f;
    float e1 = ((wrd1 >> lane) & 1u) ? expf(s1 >= 0.f ? s1 : 0.2f * s1) : 0.f;
    att2[tid] = e0;
    att2[512 + tid] = e1;
    float p0 = e0, p1 = e1;
    #pragma unroll
    for (int off = 16; off; off >>= 1) {
        p0 += __shfl_xor_sync(0xffffffffu, p0, off);
        p1 += __shfl_xor_sync(0xffffffffu, p1, off);
    }
    if (lane == 0) { red[wid] = p0; red[16 + wid] = p1; }
    __syncthreads();
    if (tid < 32) {
        float v = red[tid];
        #pragma unroll
        for (int off = 8; off; off >>= 1)
            v += __shfl_xor_sync(0xffffffffu, v, off);
        if (tid == 0)  inv[0] = 1.f / v;
        if (tid == 16) inv[1] = 1.f / v;
    }
    __syncthreads();

    {
        int r = tid >> 8, o = tid & 63, sub = (tid >> 6) & 3;
        const float* hp = g_hp2 + (size_t)b * 32768 + o;
        const float* av = att2 + r * 512 + sub * 128;
        float a0 = 0.f, a1 = 0.f, a2 = 0.f, a3 = 0.f;
        int mb = sub * 128;
        #pragma unroll 4
        for (int k = 0; k < 128; k += 4) {
            a0 = fmaf(av[k],     hp[(size_t)(mb + k) * 64],     a0);
            a1 = fmaf(av[k + 1], hp[(size_t)(mb + k + 1) * 64], a1);
            a2 = fmaf(av[k + 2], hp[(size_t)(mb + k + 2) * 64], a2);
            a3 = fmaf(av[k + 3], hp[(size_t)(mb + k + 3) * 64], a3);
        }
        part[tid] = (a0 + a1) + (a2 + a3);
    }
    __syncthreads();
    if (tid < 128) {
        int r = tid >> 6, o = tid & 63;
        float x = (part[r * 256 + o] + part[r * 256 + 64 + o] +
                   part[r * 256 + 128 + o] + part[r * 256 + 192 + o]) * inv[r] + b2[o];
        xrow[tid] = x > 0.f ? x : expm1f(x);
    }
    __syncthreads();
    if (tid < 64) {
        float vv = xrow[tid] * xrow[64 + tid];
        vsm[tid] = vv;
        out_vsm[b * 64 + tid] = vv;
    }
    __syncthreads();
    if (tid < 192) {
        float acc = fc1_b[tid];
        for (int f = 0; f < 64; f++) acc = fmaf(vsm[f], fc1_w[f * 192 + tid], acc);
        v1[tid] = fmaxf(acc, 0.f);
    }
    __syncthreads();
    if (tid < 64) {
        float acc = fc2_b[tid];
        for (int f = 0; f < 192; f++) acc = fmaf(v1[f], fc2_w[f * 64 + tid], acc);
        v2s[tid] = fmaxf(acc, 0.f);
    }
    __syncthreads();
    if (tid < 2) {
        float acc = fc3_b[tid];
        for (int f = 0; f < 64; f++) acc = fmaf(v2s[f], fc3_w[f * 2 + tid], acc);
        sc[tid] = acc;
    }
    __syncthreads();
    if (tid < 2) {
        float m = fmaxf(sc[0], sc[1]);
        float lse = m + logf(expf(sc[0] - m) + expf(sc[1] - m));
        out_scores[b * 2 + tid] = sc[tid] - lse;
    }
}

// ---------------- launch ----------------
extern "C" void kernel_launch(void* const* d_in, const int* in_sizes, int n_in,
                              void* d_out, int out_size) {
    (void)in_sizes; (void)n_in; (void)out_size;
    const float* features = (const float*)d_in[0];
    const int*   adj      = (const int*)  d_in[1];
    const float* line_emb = (const float*)d_in[5];
    const int*   v_types  = (const int*)  d_in[6];
    const float* w1       = (const float*)d_in[7];
    const float* a_src1   = (const float*)d_in[8];
    const float* a_dst1   = (const float*)d_in[9];
    const float* b1       = (const float*)d_in[10];
    const float* w2       = (const float*)d_in[11];
    const float* a_src2   = (const float*)d_in[12];
    const float* a_dst2   = (const float*)d_in[13];
    const float* b2       = (const float*)d_in[14];
    const float* fc1_w    = (const float*)d_in[15];
    const float* fc1_b    = (const float*)d_in[16];
    const float* fc2_w    = (const float*)d_in[17];
    const float* fc2_b    = (const float*)d_in[18];
    const float* fc3_w    = (const float*)d_in[19];
    const float* fc3_b    = (const float*)d_in[20];

    float* out   = (float*)d_out;
    float* vsm   = out + 64;       // v_sim_mul [32,64]
    float* attn1 = out + 2112;     // attn1 [32,8,512,512]

    cudaFuncSetAttribute(k_proj1, cudaFuncAttributeMaxDynamicSharedMemorySize, 67000);
    cudaFuncSetAttribute(k_fuse,  cudaFuncAttributeMaxDynamicSharedMemorySize, 50000);

    k_pack <<<32768, 256>>>(adj);
    k_proj1<<<dim3(8, 2, 32), 512, 66304>>>(features, line_emb, v_types, w1, a_src1, a_dst1);
    k_probe<<<1, 32>>>();
    k_fuse <<<dim3(4, 8, 32), 256, 49216>>>(b1, attn1);
    k_proj2<<<dim3(16, 32), 256>>>(v_types, w2, a_src2, a_dst2);
    k_final<<<32, 512>>>(b2, fc1_w, fc1_b, fc2_w, fc2_b, fc3_w, fc3_b, out, vsm);
}

// round 13
// speedup vs baseline: 1.2579x; 1.2376x over previous
#include <cuda_runtime.h>
#include <cuda_bf16.h>
#include <math.h>

#define NBATCH 32
#define NNODE  512
#define NHEAD  8
#define FHID   16

// ---------------- scratch (device globals; no allocations) ----------------
__device__ float    g_hp1[NBATCH*NHEAD*NNODE*FHID];   // 8 MB
__device__ float    g_as [NBATCH*NHEAD*NNODE];
__device__ float    g_Es [NBATCH*NHEAD*NNODE];
__device__ float    g_Fs [NBATCH*NHEAD*NNODE];
__device__ float    g_ad [NBATCH*NHEAD*NNODE];
__device__ float    g_Ed [NBATCH*NHEAD*NNODE];
__device__ float    g_Fd [NBATCH*NHEAD*NNODE];
__device__ float    g_inv[NBATCH*NHEAD*NNODE];        // per-row 1/sum
__device__ unsigned g_bits[NBATCH*NNODE*16];          // 1 MB bit-packed adjacency
__device__ float    g_x  [NBATCH*NNODE*128];          // 8 MB layer-2 input
__device__ float    g_hp2[NBATCH*NNODE*64];           // 4 MB
__device__ float    g_as2[NBATCH*NNODE];
__device__ float    g_ad2[NBATCH*NNODE];

// ---------------- packed f32x2 helpers (sm_103a) ----------------
static __device__ __forceinline__ unsigned long long pk2(float lo, float hi) {
    unsigned long long r;
    asm("mov.b64 %0,{%1,%2};" : "=l"(r) : "f"(lo), "f"(hi));
    return r;
}
static __device__ __forceinline__ void upk2(unsigned long long v, float& lo, float& hi) {
    asm("mov.b64 {%0,%1},%2;" : "=f"(lo), "=f"(hi) : "l"(v));
}
static __device__ __forceinline__ unsigned long long fma2(unsigned long long a,
                                                          unsigned long long b,
                                                          unsigned long long c) {
    unsigned long long d;
    asm("fma.rn.f32x2 %0,%1,%2,%3;" : "=l"(d) : "l"(a), "l"(b), "l"(c));
    return d;
}
static __device__ __forceinline__ unsigned long long add2(unsigned long long a,
                                                          unsigned long long b) {
    unsigned long long d;
    asm("add.rn.f32x2 %0,%1,%2;" : "=l"(d) : "l"(a), "l"(b));
    return d;
}

// ---------------- K0: bit-pack adjacency ----------------
__global__ void k_pack(const int* __restrict__ adj) {
    int idx = blockIdx.x * 256 + threadIdx.x;
    unsigned m = __ballot_sync(0xffffffffu, adj[idx] > 0);
    if ((threadIdx.x & 31) == 0) g_bits[idx >> 5] = m;
}

// ---------------- K1: layer-1 projection + tanh + exp tables ----------------
// grid (8, 2, 32), block 512; warp-per-node, lane owns output pair
__global__ void __launch_bounds__(512) k_proj1(
    const float* __restrict__ features, const float* __restrict__ line_emb,
    const int*   __restrict__ v_types,  const float* __restrict__ w1,
    const float* __restrict__ a_src1,   const float* __restrict__ a_dst1)
{
    extern __shared__ float sm1[];
    float* ws   = sm1;             // 12288: [t][f][l64]
    float* xv   = ws + 12288;      // 4096: 64 nodes x 64
    float* asr  = xv + 4096;       // 64
    float* ads  = asr + 64;        // 64
    int*   vt   = (int*)(ads + 64);// 64
    int tid = threadIdx.x;
    int bx = blockIdx.x, hh = blockIdx.y, b = blockIdx.z;
    int nbase = bx * 64;

    for (int i = tid; i < 12288; i += 512) {
        int l64 = i & 63, f = (i >> 6) & 63, t = i >> 12;
        int h = hh * 4 + (l64 >> 4), o = l64 & 15;
        ws[i] = w1[((t * 8 + h) * 64 + f) * 16 + o];
    }
    for (int i = tid; i < 4096; i += 512) {
        int node = i >> 6, f = i & 63;
        int n = nbase + node;
        xv[i] = (f < 32) ? features[(b * NNODE + n) * 32 + f]
                         : line_emb[(b * NNODE + n) * 32 + f - 32];
    }
    if (tid < 64) {
        int h = hh * 4 + (tid >> 4), o = tid & 15;
        asr[tid] = a_src1[h * 16 + o];
        ads[tid] = a_dst1[h * 16 + o];
        vt[tid] = v_types[b * NNODE + nbase + tid];
    }
    __syncthreads();

    int lane = tid & 31, w = tid >> 5;
    int gh = hh * 4 + (lane >> 3);
    float a0v = asr[2 * lane], a1v = asr[2 * lane + 1];
    float d0v = ads[2 * lane], d1v = ads[2 * lane + 1];
    unsigned long long z = pk2(0.f, 0.f);

    #pragma unroll
    for (int r = 0; r < 4; r++) {
        int nloc = w * 4 + r;
        int n = nbase + nloc;
        int ty = vt[nloc];
        const float* wp = ws + ty * 4096 + 2 * lane;
        const float* xp = xv + nloc * 64;
        unsigned long long acc0 = z, acc1 = z;
        #pragma unroll
        for (int f = 0; f < 64; f += 2) {
            float2 x2 = *(const float2*)&xp[f];
            unsigned long long w0 = *(const unsigned long long*)&wp[f * 64];
            unsigned long long w1v = *(const unsigned long long*)&wp[(f + 1) * 64];
            acc0 = fma2(pk2(x2.x, x2.x), w0, acc0);
            acc1 = fma2(pk2(x2.y, x2.y), w1v, acc1);
        }
        float v0, v1;
        upk2(add2(acc0, acc1), v0, v1);
        int o = (2 * lane) & 15;
        *(float2*)&g_hp1[((b * NHEAD + gh) * NNODE + n) * FHID + o] =
            make_float2(v0, v1);
        float th0 = tanhf(v0), th1 = tanhf(v1);
        float ps = th0 * a0v + th1 * a1v;
        float pd = th0 * d0v + th1 * d1v;
        #pragma unroll
        for (int off = 4; off; off >>= 1) {
            ps += __shfl_xor_sync(0xffffffffu, ps, off);
            pd += __shfl_xor_sync(0xffffffffu, pd, off);
        }
        if ((lane & 7) == 0) {
            int ai = (b * NHEAD + gh) * NNODE + n;
            g_as[ai] = ps; g_Es[ai] = expf(ps); g_Fs[ai] = expf(0.2f * ps);
            g_ad[ai] = pd; g_Ed[ai] = expf(pd); g_Fd[ai] = expf(0.2f * pd);
        }
    }
}

// ---------------- K2a: attn numerators + row sums + COALESCED attn1 store ----------------
// grid (2, 8, 32) = (nhalf, h, b), 256 threads = 8 warps, warp-per-row (32 rows each).
// Lane owns columns m = 4*lane + c + 128*k (c,k in 0..3); tbl held in registers.
__global__ void __launch_bounds__(256) k_store(float* __restrict__ attn_out) {
    __shared__ float4   rc_s[256];        // (as, Es, Fs, 0) for block's rows
    __shared__ float4   tbl_s[512];       // (ad, Ed, Fd, 0) all columns
    __shared__ unsigned bits_s[256 * 16]; // [row][w]
    int tid = threadIdx.x;
    int nh = blockIdx.x, h = blockIdx.y, b = blockIdx.z;
    int bh = b * NHEAD + h;
    int n0 = nh * 256;

    for (int i = tid; i < 256; i += 256)
        rc_s[i] = make_float4(g_as[bh * 512 + n0 + i], g_Es[bh * 512 + n0 + i],
                              g_Fs[bh * 512 + n0 + i], 0.f);
    for (int i = tid; i < 512; i += 256)
        tbl_s[i] = make_float4(g_ad[bh * 512 + i], g_Ed[bh * 512 + i],
                               g_Fd[bh * 512 + i], 0.f);
    for (int i = tid; i < 4096; i += 256)
        bits_s[i] = g_bits[b * 8192 + n0 * 16 + i];
    __syncthreads();

    int lane = tid & 31, w = tid >> 5;
    float ad[16], Ed[16], Fd[16];
    #pragma unroll
    for (int k = 0; k < 4; k++)
        #pragma unroll
        for (int c = 0; c < 4; c++) {
            float4 t = tbl_s[4 * lane + c + 128 * k];
            ad[4 * k + c] = t.x; Ed[4 * k + c] = t.y; Fd[4 * k + c] = t.z;
        }
    unsigned mask[4];
    #pragma unroll
    for (int c = 0; c < 4; c++) mask[c] = 1u << (((lane & 7) * 4) + c);
    int wbase = lane >> 3;

    float* obase = attn_out + (size_t)bh * 512 * 512;
    for (int r = 0; r < 32; r++) {
        int lrow = w * 32 + r;
        int grow = n0 + lrow;
        float4 rc = rc_s[lrow];
        float nb[16];
        float sum = 0.f;
        #pragma unroll
        for (int k = 0; k < 4; k++) {
            unsigned wa = bits_s[lrow * 16 + wbase + 4 * k];
            #pragma unroll
            for (int c = 0; c < 4; c++) {
                int i = 4 * k + c;
                float sa = rc.x + ad[i];
                float t  = (sa >= 0.f) ? Ed[i] : Fd[i];
                float cc = (sa >= 0.f) ? rc.y : rc.z;
                float n  = (wa & mask[c]) ? t * cc : 0.f;
                nb[i] = n;
                sum += n;
            }
        }
        #pragma unroll
        for (int off = 16; off; off >>= 1)
            sum += __shfl_xor_sync(0xffffffffu, sum, off);
        float inva = 1.f / sum;
        if (lane == 0) g_inv[bh * 512 + grow] = inva;
        float* rp = obase + (size_t)grow * 512 + 4 * lane;
        #pragma unroll
        for (int k = 0; k < 4; k++)
            __stcs((float4*)(rp + 128 * k),
                   make_float4(nb[4*k] * inva, nb[4*k+1] * inva,
                               nb[4*k+2] * inva, nb[4*k+3] * inva));
    }
}

// ---------------- K2b: out1 GEMM (attn recomputed, NO stores) + elu -> g_x ----------------
// grid (2, 8, 32), 256 threads (1 row/thread), dyn smem 57408 B (R10 layout)
__global__ void __launch_bounds__(256) k_gemm(const float* __restrict__ b1) {
    extern __shared__ float smf[];
    float*    hp_s   = smf;                       // 8192 floats [m][o]
    float4*   tbl    = (float4*)(smf + 8192);     // 512 float4 (ad, Ed, Fd, 0)
    unsigned* bits_s = (unsigned*)(smf + 10240);  // 4096 words, layout [w][r]
    float*    b1s    = smf + 14336;               // 16
    int tid = threadIdx.x;
    int nh = blockIdx.x, h = blockIdx.y, b = blockIdx.z;
    int bh = b * NHEAD + h;
    int n0 = nh * 256;

    for (int i = tid; i < 8192; i += 256) hp_s[i] = g_hp1[bh * 8192 + i];
    for (int i = tid; i < 512; i += 256)
        tbl[i] = make_float4(g_ad[bh * 512 + i], g_Ed[bh * 512 + i],
                             g_Fd[bh * 512 + i], 0.f);
    for (int i = tid; i < 4096; i += 256) {
        int w = i >> 8, r = i & 255;
        bits_s[i] = g_bits[b * 8192 + (n0 + r) * 16 + w];
    }
    if (tid < 16) b1s[tid] = b1[tid];

    int na = n0 + tid;
    float as_a = g_as[bh * 512 + na];
    float inva = g_inv[bh * 512 + na];
    float Esa = g_Es[bh * 512 + na] * inva;
    float Fsa = g_Fs[bh * 512 + na] * inva;
    __syncthreads();

    unsigned long long acc[8];
    unsigned long long z = pk2(0.f, 0.f);
    #pragma unroll
    for (int q = 0; q < 8; q++) acc[q] = z;

    for (int mw = 0; mw < 16; mw++) {
        unsigned wa = bits_s[mw * 256 + tid];
        #pragma unroll
        for (int mi = 0; mi < 32; mi++) {
            int m = mw * 32 + mi;
            float4 t = tbl[m];
            float sa = as_a + t.x;
            float ca = (sa >= 0.f) ? Esa : Fsa;
            if (!((wa >> mi) & 1u)) ca = 0.f;
            float ea = ca * ((sa >= 0.f) ? t.y : t.z);
            unsigned long long pa = pk2(ea, ea);
            const unsigned long long* hq =
                (const unsigned long long*)(hp_s + m * 16);
            #pragma unroll
            for (int q = 0; q < 8; q++)
                acc[q] = fma2(pa, hq[q], acc[q]);
        }
    }

    float va[16];
    #pragma unroll
    for (int q = 0; q < 8; q++)
        upk2(acc[q], va[2 * q], va[2 * q + 1]);
    float ra[16];
    #pragma unroll
    for (int k = 0; k < 16; k++) {
        float xa = va[k] + b1s[k];
        ra[k] = xa > 0.f ? xa : expm1f(xa);
    }
    float* da = &g_x[(size_t)(b * 512 + na) * 128 + h * 16];
    #pragma unroll
    for (int q = 0; q < 4; q++)
        ((float4*)da)[q] = make_float4(ra[4*q], ra[4*q+1], ra[4*q+2], ra[4*q+3]);
}

// ---------------- K3: layer-2 projection; LDG.128 weights, quad-per-lane ----------------
__global__ void __launch_bounds__(256, 2) k_proj2(
    const int* __restrict__ v_types, const float* __restrict__ w2,
    const float* __restrict__ a_src2, const float* __restrict__ a_dst2)
{
    __shared__ float xv[32 * 128];
    __shared__ float asw[64], adw[64];
    __shared__ int   vt[32];
    int tid = threadIdx.x, b = blockIdx.y, bx = blockIdx.x;
    int nbase = bx * 32;

    for (int i = tid; i < 4096; i += 256)
        xv[i] = g_x[(size_t)(b * 512 + nbase) * 128 + i];
    if (tid < 64) { asw[tid] = a_src2[tid]; adw[tid] = a_dst2[tid]; }
    if (tid < 32) vt[tid] = v_types[b * 512 + nbase + tid];
    __syncthreads();

    int lane = tid & 31, w = tid >> 5;
    int half = lane >> 4, l16 = lane & 15;
    int o = l16 * 4;
    float a0v = asw[o], a1v = asw[o + 1], a2v = asw[o + 2], a3v = asw[o + 3];
    float d0v = adw[o], d1v = adw[o + 1], d2v = adw[o + 2], d3v = adw[o + 3];
    unsigned long long z = pk2(0.f, 0.f);

    #pragma unroll
    for (int pass = 0; pass < 2; pass++) {
        int nloc = pass * 16 + w * 2 + half;
        int n = nbase + nloc;
        int ty = vt[nloc];
        const float4* wp = (const float4*)(w2 + ty * 8192 + o);
        const float* xp = xv + nloc * 128;
        unsigned long long acc01 = z, acc23 = z;
        #pragma unroll
        for (int c = 0; c < 16; c++) {
            float4 wb[8];
            #pragma unroll
            for (int j = 0; j < 8; j++)
                wb[j] = __ldg(wp + (c * 8 + j) * 16);
            float4 xa = *(const float4*)&xp[c * 8];
            float4 xc = *(const float4*)&xp[c * 8 + 4];
            float xs[8] = {xa.x, xa.y, xa.z, xa.w, xc.x, xc.y, xc.z, xc.w};
            #pragma unroll
            for (int j = 0; j < 8; j++) {
                unsigned long long xx = pk2(xs[j], xs[j]);
                acc01 = fma2(xx, pk2(wb[j].x, wb[j].y), acc01);
                acc23 = fma2(xx, pk2(wb[j].z, wb[j].w), acc23);
            }
        }
        float v0, v1, v2, v3;
        upk2(acc01, v0, v1);
        upk2(acc23, v2, v3);
        *(float4*)&g_hp2[(size_t)(b * 512 + n) * 64 + o] =
            make_float4(v0, v1, v2, v3);
        float th0 = tanhf(v0), th1 = tanhf(v1), th2 = tanhf(v2), th3 = tanhf(v3);
        float ps = th0 * a0v + th1 * a1v + th2 * a2v + th3 * a3v;
        float pd = th0 * d0v + th1 * d1v + th2 * d2v + th3 * d3v;
        #pragma unroll
        for (int off = 8; off; off >>= 1) {
            ps += __shfl_xor_sync(0xffffffffu, ps, off);
            pd += __shfl_xor_sync(0xffffffffu, pd, off);
        }
        if (l16 == 0) {
            g_as2[b * 512 + n] = ps;
            g_ad2[b * 512 + n] = pd;
        }
    }
}

// ---------------- K4: layer-2 rows 0/1 + MLP + log_softmax ----------------
__global__ void __launch_bounds__(512) k_final(
    const float* __restrict__ b2,
    const float* __restrict__ fc1_w, const float* __restrict__ fc1_b,
    const float* __restrict__ fc2_w, const float* __restrict__ fc2_b,
    const float* __restrict__ fc3_w, const float* __restrict__ fc3_b,
    float* __restrict__ out_scores, float* __restrict__ out_vsm)
{
    __shared__ float att2[2 * 512];
    __shared__ float inv[2];
    __shared__ float part[512];
    __shared__ float xrow[128];
    __shared__ float vsm[64], v1[192], v2s[64];
    __shared__ float red[32];
    __shared__ float sc[2];
    int tid = threadIdx.x, b = blockIdx.x;
    int lane = tid & 31, wid = tid >> 5;

    float ad2 = g_ad2[b * 512 + tid];
    unsigned wrd  = g_bits[b * 8192 + (tid >> 5)];
    unsigned wrd1 = g_bits[b * 8192 + 16 + (tid >> 5)];
    float as0 = g_as2[b * 512 + 0], as1 = g_as2[b * 512 + 1];
    float s0 = as0 + ad2, s1 = as1 + ad2;
    float e0 = ((wrd  >> lane) & 1u) ? expf(s0 >= 0.f ? s0 : 0.2f * s0) : 0.f;
    float e1 = ((wrd1 >> lane) & 1u) ? expf(s1 >= 0.f ? s1 : 0.2f * s1) : 0.f;
    att2[tid] = e0;
    att2[512 + tid] = e1;
    float p0 = e0, p1 = e1;
    #pragma unroll
    for (int off = 16; off; off >>= 1) {
        p0 += __shfl_xor_sync(0xffffffffu, p0, off);
        p1 += __shfl_xor_sync(0xffffffffu, p1, off);
    }
    if (lane == 0) { red[wid] = p0; red[16 + wid] = p1; }
    __syncthreads();
    if (tid < 32) {
        float v = red[tid];
        #pragma unroll
        for (int off = 8; off; off >>= 1)
            v += __shfl_xor_sync(0xffffffffu, v, off);
        if (tid == 0)  inv[0] = 1.f / v;
        if (tid == 16) inv[1] = 1.f / v;
    }
    __syncthreads();

    {
        int r = tid >> 8, o = tid & 63, sub = (tid >> 6) & 3;
        const float* hp = g_hp2 + (size_t)b * 32768 + o;
        const float* av = att2 + r * 512 + sub * 128;
        float a0 = 0.f, a1 = 0.f, a2 = 0.f, a3 = 0.f;
        int mb = sub * 128;
        #pragma unroll 4
        for (int k = 0; k < 128; k += 4) {
            a0 = fmaf(av[k],     hp[(size_t)(mb + k) * 64],     a0);
            a1 = fmaf(av[k + 1], hp[(size_t)(mb + k + 1) * 64], a1);
            a2 = fmaf(av[k + 2], hp[(size_t)(mb + k + 2) * 64], a2);
            a3 = fmaf(av[k + 3], hp[(size_t)(mb + k + 3) * 64], a3);
        }
        part[tid] = (a0 + a1) + (a2 + a3);
    }
    __syncthreads();
    if (tid < 128) {
        int r = tid >> 6, o = tid & 63;
        float x = (part[r * 256 + o] + part[r * 256 + 64 + o] +
                   part[r * 256 + 128 + o] + part[r * 256 + 192 + o]) * inv[r] + b2[o];
        xrow[tid] = x > 0.f ? x : expm1f(x);
    }
    __syncthreads();
    if (tid < 64) {
        float vv = xrow[tid] * xrow[64 + tid];
        vsm[tid] = vv;
        out_vsm[b * 64 + tid] = vv;
    }
    __syncthreads();
    if (tid < 192) {
        float acc = fc1_b[tid];
        for (int f = 0; f < 64; f++) acc = fmaf(vsm[f], fc1_w[f * 192 + tid], acc);
        v1[tid] = fmaxf(acc, 0.f);
    }
    __syncthreads();
    if (tid < 64) {
        float acc = fc2_b[tid];
        for (int f = 0; f < 192; f++) acc = fmaf(v1[f], fc2_w[f * 64 + tid], acc);
        v2s[tid] = fmaxf(acc, 0.f);
    }
    __syncthreads();
    if (tid < 2) {
        float acc = fc3_b[tid];
        for (int f = 0; f < 64; f++) acc = fmaf(v2s[f], fc3_w[f * 2 + tid], acc);
        sc[tid] = acc;
    }
    __syncthreads();
    if (tid < 2) {
        float m = fmaxf(sc[0], sc[1]);
        float lse = m + logf(expf(sc[0] - m) + expf(sc[1] - m));
        out_scores[b * 2 + tid] = sc[tid] - lse;
    }
}

// ---------------- launch ----------------
extern "C" void kernel_launch(void* const* d_in, const int* in_sizes, int n_in,
                              void* d_out, int out_size) {
    (void)in_sizes; (void)n_in; (void)out_size;
    const float* features = (const float*)d_in[0];
    const int*   adj      = (const int*)  d_in[1];
    const float* line_emb = (const float*)d_in[5];
    const int*   v_types  = (const int*)  d_in[6];
    const float* w1       = (const float*)d_in[7];
    const float* a_src1   = (const float*)d_in[8];
    const float* a_dst1   = (const float*)d_in[9];
    const float* b1       = (const float*)d_in[10];
    const float* w2       = (const float*)d_in[11];
    const float* a_src2   = (const float*)d_in[12];
    const float* a_dst2   = (const float*)d_in[13];
    const float* b2       = (const float*)d_in[14];
    const float* fc1_w    = (const float*)d_in[15];
    const float* fc1_b    = (const float*)d_in[16];
    const float* fc2_w    = (const float*)d_in[17];
    const float* fc2_b    = (const float*)d_in[18];
    const float* fc3_w    = (const float*)d_in[19];
    const float* fc3_b    = (const float*)d_in[20];

    float* out   = (float*)d_out;
    float* vsm   = out + 64;       // v_sim_mul [32,64]
    float* attn1 = out + 2112;     // attn1 [32,8,512,512]

    cudaFuncSetAttribute(k_proj1, cudaFuncAttributeMaxDynamicSharedMemorySize, 67000);
    cudaFuncSetAttribute(k_gemm,  cudaFuncAttributeMaxDynamicSharedMemorySize, 58000);

    k_pack <<<32768, 256>>>(adj);
    k_proj1<<<dim3(8, 2, 32), 512, 66304>>>(features, line_emb, v_types, w1, a_src1, a_dst1);
    k_store<<<dim3(2, 8, 32), 256>>>(attn1);
    k_gemm <<<dim3(2, 8, 32), 256, 57408>>>(b1);
    k_proj2<<<dim3(16, 32), 256>>>(v_types, w2, a_src2, a_dst2);
    k_final<<<32, 512>>>(b2, fc1_w, fc1_b, fc2_w, fc2_b, fc3_w, fc3_b, out, vsm);
}

// round 14
// speedup vs baseline: 1.4000x; 1.1130x over previous
#include <cuda_runtime.h>
#include <cuda_bf16.h>
#include <math.h>

#define NBATCH 32
#define NNODE  512
#define NHEAD  8
#define FHID   16

// ---------------- scratch (device globals; no allocations) ----------------
__device__ float    g_hp1[NBATCH*NHEAD*NNODE*FHID];   // 8 MB
__device__ float    g_as [NBATCH*NHEAD*NNODE];
__device__ float    g_Es [NBATCH*NHEAD*NNODE];
__device__ float    g_Fs [NBATCH*NHEAD*NNODE];
__device__ float    g_ad [NBATCH*NHEAD*NNODE];
__device__ float    g_Ed [NBATCH*NHEAD*NNODE];
__device__ float    g_Fd [NBATCH*NHEAD*NNODE];
__device__ float    g_inv[NBATCH*NHEAD*NNODE];        // per-row 1/sum
__device__ unsigned g_bits[NBATCH*NNODE*16];          // 1 MB bit-packed adjacency
__device__ float    g_x  [NBATCH*NNODE*128];          // 8 MB layer-2 input
__device__ float    g_hp2[NBATCH*NNODE*64];           // 4 MB
__device__ float    g_as2[NBATCH*NNODE];
__device__ float    g_ad2[NBATCH*NNODE];

// ---------------- packed f32x2 helpers (sm_103a) ----------------
static __device__ __forceinline__ unsigned long long pk2(float lo, float hi) {
    unsigned long long r;
    asm("mov.b64 %0,{%1,%2};" : "=l"(r) : "f"(lo), "f"(hi));
    return r;
}
static __device__ __forceinline__ void upk2(unsigned long long v, float& lo, float& hi) {
    asm("mov.b64 {%0,%1},%2;" : "=f"(lo), "=f"(hi) : "l"(v));
}
static __device__ __forceinline__ unsigned long long fma2(unsigned long long a,
                                                          unsigned long long b,
                                                          unsigned long long c) {
    unsigned long long d;
    asm("fma.rn.f32x2 %0,%1,%2,%3;" : "=l"(d) : "l"(a), "l"(b), "l"(c));
    return d;
}
static __device__ __forceinline__ unsigned long long add2(unsigned long long a,
                                                          unsigned long long b) {
    unsigned long long d;
    asm("add.rn.f32x2 %0,%1,%2;" : "=l"(d) : "l"(a), "l"(b));
    return d;
}

// ---------------- K0: bit-pack adjacency ----------------
__global__ void k_pack(const int* __restrict__ adj) {
    int idx = blockIdx.x * 256 + threadIdx.x;
    unsigned m = __ballot_sync(0xffffffffu, adj[idx] > 0);
    if ((threadIdx.x & 31) == 0) g_bits[idx >> 5] = m;
}

// ---------------- K1: layer-1 projection + tanh + exp tables ----------------
// grid (8, 2, 32), block 512; warp-per-node, lane owns output pair
__global__ void __launch_bounds__(512) k_proj1(
    const float* __restrict__ features, const float* __restrict__ line_emb,
    const int*   __restrict__ v_types,  const float* __restrict__ w1,
    const float* __restrict__ a_src1,   const float* __restrict__ a_dst1)
{
    extern __shared__ float sm1[];
    float* ws   = sm1;             // 12288: [t][f][l64]
    float* xv   = ws + 12288;      // 4096: 64 nodes x 64
    float* asr  = xv + 4096;       // 64
    float* ads  = asr + 64;        // 64
    int*   vt   = (int*)(ads + 64);// 64
    int tid = threadIdx.x;
    int bx = blockIdx.x, hh = blockIdx.y, b = blockIdx.z;
    int nbase = bx * 64;

    for (int i = tid; i < 12288; i += 512) {
        int l64 = i & 63, f = (i >> 6) & 63, t = i >> 12;
        int h = hh * 4 + (l64 >> 4), o = l64 & 15;
        ws[i] = w1[((t * 8 + h) * 64 + f) * 16 + o];
    }
    for (int i = tid; i < 4096; i += 512) {
        int node = i >> 6, f = i & 63;
        int n = nbase + node;
        xv[i] = (f < 32) ? features[(b * NNODE + n) * 32 + f]
                         : line_emb[(b * NNODE + n) * 32 + f - 32];
    }
    if (tid < 64) {
        int h = hh * 4 + (tid >> 4), o = tid & 15;
        asr[tid] = a_src1[h * 16 + o];
        ads[tid] = a_dst1[h * 16 + o];
        vt[tid] = v_types[b * NNODE + nbase + tid];
    }
    __syncthreads();

    int lane = tid & 31, w = tid >> 5;
    int gh = hh * 4 + (lane >> 3);
    float a0v = asr[2 * lane], a1v = asr[2 * lane + 1];
    float d0v = ads[2 * lane], d1v = ads[2 * lane + 1];
    unsigned long long z = pk2(0.f, 0.f);

    #pragma unroll
    for (int r = 0; r < 4; r++) {
        int nloc = w * 4 + r;
        int n = nbase + nloc;
        int ty = vt[nloc];
        const float* wp = ws + ty * 4096 + 2 * lane;
        const float* xp = xv + nloc * 64;
        unsigned long long acc0 = z, acc1 = z;
        #pragma unroll
        for (int f = 0; f < 64; f += 2) {
            float2 x2 = *(const float2*)&xp[f];
            unsigned long long w0 = *(const unsigned long long*)&wp[f * 64];
            unsigned long long w1v = *(const unsigned long long*)&wp[(f + 1) * 64];
            acc0 = fma2(pk2(x2.x, x2.x), w0, acc0);
            acc1 = fma2(pk2(x2.y, x2.y), w1v, acc1);
        }
        float v0, v1;
        upk2(add2(acc0, acc1), v0, v1);
        int o = (2 * lane) & 15;
        *(float2*)&g_hp1[((b * NHEAD + gh) * NNODE + n) * FHID + o] =
            make_float2(v0, v1);
        float th0 = tanhf(v0), th1 = tanhf(v1);
        float ps = th0 * a0v + th1 * a1v;
        float pd = th0 * d0v + th1 * d1v;
        #pragma unroll
        for (int off = 4; off; off >>= 1) {
            ps += __shfl_xor_sync(0xffffffffu, ps, off);
            pd += __shfl_xor_sync(0xffffffffu, pd, off);
        }
        if ((lane & 7) == 0) {
            int ai = (b * NHEAD + gh) * NNODE + n;
            g_as[ai] = ps; g_Es[ai] = expf(ps); g_Fs[ai] = expf(0.2f * ps);
            g_ad[ai] = pd; g_Ed[ai] = expf(pd); g_Fd[ai] = expf(0.2f * pd);
        }
    }
}

// ---------------- K2a: attn numerators + row sums + COALESCED attn1 store ----------------
// grid (2, 8, 32) = (nhalf, h, b), 256 threads = 8 warps, warp-per-row (32 rows each).
__global__ void __launch_bounds__(256) k_store(float* __restrict__ attn_out) {
    __shared__ float4   rc_s[256];        // (as, Es, Fs, 0) for block's rows
    __shared__ float4   tbl_s[512];       // (ad, Ed, Fd, 0) all columns
    __shared__ unsigned bits_s[256 * 16]; // [row][w]
    int tid = threadIdx.x;
    int nh = blockIdx.x, h = blockIdx.y, b = blockIdx.z;
    int bh = b * NHEAD + h;
    int n0 = nh * 256;

    for (int i = tid; i < 256; i += 256)
        rc_s[i] = make_float4(g_as[bh * 512 + n0 + i], g_Es[bh * 512 + n0 + i],
                              g_Fs[bh * 512 + n0 + i], 0.f);
    for (int i = tid; i < 512; i += 256)
        tbl_s[i] = make_float4(g_ad[bh * 512 + i], g_Ed[bh * 512 + i],
                               g_Fd[bh * 512 + i], 0.f);
    for (int i = tid; i < 4096; i += 256)
        bits_s[i] = g_bits[b * 8192 + n0 * 16 + i];
    __syncthreads();

    int lane = tid & 31, w = tid >> 5;
    float ad[16], Ed[16], Fd[16];
    #pragma unroll
    for (int k = 0; k < 4; k++)
        #pragma unroll
        for (int c = 0; c < 4; c++) {
            float4 t = tbl_s[4 * lane + c + 128 * k];
            ad[4 * k + c] = t.x; Ed[4 * k + c] = t.y; Fd[4 * k + c] = t.z;
        }
    unsigned mask[4];
    #pragma unroll
    for (int c = 0; c < 4; c++) mask[c] = 1u << (((lane & 7) * 4) + c);
    int wbase = lane >> 3;

    float* obase = attn_out + (size_t)bh * 512 * 512;
    for (int r = 0; r < 32; r++) {
        int lrow = w * 32 + r;
        int grow = n0 + lrow;
        float4 rc = rc_s[lrow];
        float nb[16];
        float sum = 0.f;
        #pragma unroll
        for (int k = 0; k < 4; k++) {
            unsigned wa = bits_s[lrow * 16 + wbase + 4 * k];
            #pragma unroll
            for (int c = 0; c < 4; c++) {
                int i = 4 * k + c;
                float sa = rc.x + ad[i];
                float t  = (sa >= 0.f) ? Ed[i] : Fd[i];
                float cc = (sa >= 0.f) ? rc.y : rc.z;
                float n  = (wa & mask[c]) ? t * cc : 0.f;
                nb[i] = n;
                sum += n;
            }
        }
        #pragma unroll
        for (int off = 16; off; off >>= 1)
            sum += __shfl_xor_sync(0xffffffffu, sum, off);
        float inva = 1.f / sum;
        if (lane == 0) g_inv[bh * 512 + grow] = inva;
        float* rp = obase + (size_t)grow * 512 + 4 * lane;
        #pragma unroll
        for (int k = 0; k < 4; k++)
            __stcs((float4*)(rp + 128 * k),
                   make_float4(nb[4*k] * inva, nb[4*k+1] * inva,
                               nb[4*k+2] * inva, nb[4*k+3] * inva));
    }
}

// ---------------- K2b: out1 GEMM, 2 rows/thread (attn recomputed, no stores) ----------------
// grid (8, 32) = (h, b), 256 threads, rows 2t/2t+1; dyn smem 73792 B, 3 blocks/SM
__global__ void __launch_bounds__(256, 3) k_gemm(const float* __restrict__ b1) {
    extern __shared__ float smf[];
    float*    hp_s   = smf;                       // 8192 floats [m][o]
    float4*   tbl    = (float4*)(smf + 8192);     // 512 float4 (ad, Ed, Fd, 0)
    unsigned* bits_s = (unsigned*)(smf + 10240);  // 8192 words, layout [w][r], 512 rows
    float*    b1s    = smf + 18432;               // 16
    int tid = threadIdx.x;
    int h = blockIdx.x, b = blockIdx.y;
    int bh = b * NHEAD + h;

    for (int i = tid; i < 8192; i += 256) hp_s[i] = g_hp1[bh * 8192 + i];
    for (int i = tid; i < 512; i += 256)
        tbl[i] = make_float4(g_ad[bh * 512 + i], g_Ed[bh * 512 + i],
                             g_Fd[bh * 512 + i], 0.f);
    for (int i = tid; i < 8192; i += 256) {
        int w = i >> 9, r = i & 511;
        bits_s[i] = g_bits[b * 8192 + r * 16 + w];
    }
    if (tid < 16) b1s[tid] = b1[tid];

    int na = 2 * tid, nb = na + 1;
    float as_a = g_as[bh * 512 + na], as_b = g_as[bh * 512 + nb];
    float iva = g_inv[bh * 512 + na], ivb = g_inv[bh * 512 + nb];
    float Esa = g_Es[bh * 512 + na] * iva, Fsa = g_Fs[bh * 512 + na] * iva;
    float Esb = g_Es[bh * 512 + nb] * ivb, Fsb = g_Fs[bh * 512 + nb] * ivb;
    __syncthreads();

    unsigned long long acc[16];
    unsigned long long z = pk2(0.f, 0.f);
    #pragma unroll
    for (int q = 0; q < 16; q++) acc[q] = z;

    for (int mw = 0; mw < 16; mw++) {
        unsigned wa = bits_s[mw * 512 + na];
        unsigned wb = bits_s[mw * 512 + nb];
        #pragma unroll
        for (int mi = 0; mi < 32; mi++) {
            int m = mw * 32 + mi;
            float4 t = tbl[m];
            float sa = as_a + t.x, sb = as_b + t.x;
            float ca = (sa >= 0.f) ? Esa : Fsa;
            float cb = (sb >= 0.f) ? Esb : Fsb;
            if (!((wa >> mi) & 1u)) ca = 0.f;
            if (!((wb >> mi) & 1u)) cb = 0.f;
            float ea = ca * ((sa >= 0.f) ? t.y : t.z);
            float eb = cb * ((sb >= 0.f) ? t.y : t.z);
            unsigned long long pa = pk2(ea, ea);
            unsigned long long pb = pk2(eb, eb);
            const unsigned long long* hq =
                (const unsigned long long*)(hp_s + m * 16);
            #pragma unroll
            for (int q = 0; q < 8; q++) {
                acc[q]     = fma2(pa, hq[q], acc[q]);
                acc[8 + q] = fma2(pb, hq[q], acc[8 + q]);
            }
        }
    }

    float va[16], vb[16];
    #pragma unroll
    for (int q = 0; q < 8; q++) {
        upk2(acc[q],     va[2 * q], va[2 * q + 1]);
        upk2(acc[8 + q], vb[2 * q], vb[2 * q + 1]);
    }
    float ra[16], rb[16];
    #pragma unroll
    for (int k = 0; k < 16; k++) {
        float xa = va[k] + b1s[k];
        float xb = vb[k] + b1s[k];
        ra[k] = xa > 0.f ? xa : expm1f(xa);
        rb[k] = xb > 0.f ? xb : expm1f(xb);
    }
    float* da = &g_x[(size_t)(b * 512 + na) * 128 + h * 16];
    float* db = &g_x[(size_t)(b * 512 + nb) * 128 + h * 16];
    #pragma unroll
    for (int q = 0; q < 4; q++) {
        ((float4*)da)[q] = make_float4(ra[4*q], ra[4*q+1], ra[4*q+2], ra[4*q+3]);
        ((float4*)db)[q] = make_float4(rb[4*q], rb[4*q+1], rb[4*q+2], rb[4*q+3]);
    }
}

// ---------------- K3: layer-2 projection; LDG.128 weights, quad-per-lane ----------------
__global__ void __launch_bounds__(256, 2) k_proj2(
    const int* __restrict__ v_types, const float* __restrict__ w2,
    const float* __restrict__ a_src2, const float* __restrict__ a_dst2)
{
    __shared__ float xv[32 * 128];
    __shared__ float asw[64], adw[64];
    __shared__ int   vt[32];
    int tid = threadIdx.x, b = blockIdx.y, bx = blockIdx.x;
    int nbase = bx * 32;

    for (int i = tid; i < 4096; i += 256)
        xv[i] = g_x[(size_t)(b * 512 + nbase) * 128 + i];
    if (tid < 64) { asw[tid] = a_src2[tid]; adw[tid] = a_dst2[tid]; }
    if (tid < 32) vt[tid] = v_types[b * 512 + nbase + tid];
    __syncthreads();

    int lane = tid & 31, w = tid >> 5;
    int half = lane >> 4, l16 = lane & 15;
    int o = l16 * 4;
    float a0v = asw[o], a1v = asw[o + 1], a2v = asw[o + 2], a3v = asw[o + 3];
    float d0v = adw[o], d1v = adw[o + 1], d2v = adw[o + 2], d3v = adw[o + 3];
    unsigned long long z = pk2(0.f, 0.f);

    #pragma unroll
    for (int pass = 0; pass < 2; pass++) {
        int nloc = pass * 16 + w * 2 + half;
        int n = nbase + nloc;
        int ty = vt[nloc];
        const float4* wp = (const float4*)(w2 + ty * 8192 + o);
        const float* xp = xv + nloc * 128;
        unsigned long long acc01 = z, acc23 = z;
        #pragma unroll
        for (int c = 0; c < 16; c++) {
            float4 wb[8];
            #pragma unroll
            for (int j = 0; j < 8; j++)
                wb[j] = __ldg(wp + (c * 8 + j) * 16);
            float4 xa = *(const float4*)&xp[c * 8];
            float4 xc = *(const float4*)&xp[c * 8 + 4];
            float xs[8] = {xa.x, xa.y, xa.z, xa.w, xc.x, xc.y, xc.z, xc.w};
            #pragma unroll
            for (int j = 0; j < 8; j++) {
                unsigned long long xx = pk2(xs[j], xs[j]);
                acc01 = fma2(xx, pk2(wb[j].x, wb[j].y), acc01);
                acc23 = fma2(xx, pk2(wb[j].z, wb[j].w), acc23);
            }
        }
        float v0, v1, v2, v3;
        upk2(acc01, v0, v1);
        upk2(acc23, v2, v3);
        *(float4*)&g_hp2[(size_t)(b * 512 + n) * 64 + o] =
            make_float4(v0, v1, v2, v3);
        float th0 = tanhf(v0), th1 = tanhf(v1), th2 = tanhf(v2), th3 = tanhf(v3);
        float ps = th0 * a0v + th1 * a1v + th2 * a2v + th3 * a3v;
        float pd = th0 * d0v + th1 * d1v + th2 * d2v + th3 * d3v;
        #pragma unroll
        for (int off = 8; off; off >>= 1) {
            ps += __shfl_xor_sync(0xffffffffu, ps, off);
            pd += __shfl_xor_sync(0xffffffffu, pd, off);
        }
        if (l16 == 0) {
            g_as2[b * 512 + n] = ps;
            g_ad2[b * 512 + n] = pd;
        }
    }
}

// ---------------- K4: layer-2 rows 0/1 + MLP + log_softmax ----------------
__global__ void __launch_bounds__(512) k_final(
    const float* __restrict__ b2,
    const float* __restrict__ fc1_w, const float* __restrict__ fc1_b,
    const float* __restrict__ fc2_w, const float* __restrict__ fc2_b,
    const float* __restrict__ fc3_w, const float* __restrict__ fc3_b,
    float* __restrict__ out_scores, float* __restrict__ out_vsm)
{
    __shared__ float att2[2 * 512];
    __shared__ float inv[2];
    __shared__ float part[512];
    __shared__ float xrow[128];
    __shared__ float vsm[64], v1[192], v2s[64];
    __shared__ float red[32];
    __shared__ float sc[2];
    int tid = threadIdx.x, b = blockIdx.x;
    int lane = tid & 31, wid = tid >> 5;

    float ad2 = g_ad2[b * 512 + tid];
    unsigned wrd  = g_bits[b * 8192 + (tid >> 5)];
    unsigned wrd1 = g_bits[b * 8192 + 16 + (tid >> 5)];
    float as0 = g_as2[b * 512 + 0], as1 = g_as2[b * 512 + 1];
    float s0 = as0 + ad2, s1 = as1 + ad2;
    float e0 = ((wrd  >> lane) & 1u) ? expf(s0 >= 0.f ? s0 : 0.2f * s0) : 0.f;
    float e1 = ((wrd1 >> lane) & 1u) ? expf(s1 >= 0.f ? s1 : 0.2f * s1) : 0.f;
    att2[tid] = e0;
    att2[512 + tid] = e1;
    float p0 = e0, p1 = e1;
    #pragma unroll
    for (int off = 16; off; off >>= 1) {
        p0 += __shfl_xor_sync(0xffffffffu, p0, off);
        p1 += __shfl_xor_sync(0xffffffffu, p1, off);
    }
    if (lane == 0) { red[wid] = p0; red[16 + wid] = p1; }
    __syncthreads();
    if (tid < 32) {
        float v = red[tid];
        #pragma unroll
        for (int off = 8; off; off >>= 1)
            v += __shfl_xor_sync(0xffffffffu, v, off);
        if (tid == 0)  inv[0] = 1.f / v;
        if (tid == 16) inv[1] = 1.f / v;
    }
    __syncthreads();

    {
        int r = tid >> 8, o = tid & 63, sub = (tid >> 6) & 3;
        const float* hp = g_hp2 + (size_t)b * 32768 + o;
        const float* av = att2 + r * 512 + sub * 128;
        float a0 = 0.f, a1 = 0.f, a2 = 0.f, a3 = 0.f;
        int mb = sub * 128;
        #pragma unroll 4
        for (int k = 0; k < 128; k += 4) {
            a0 = fmaf(av[k],     hp[(size_t)(mb + k) * 64],     a0);
            a1 = fmaf(av[k + 1], hp[(size_t)(mb + k + 1) * 64], a1);
            a2 = fmaf(av[k + 2], hp[(size_t)(mb + k + 2) * 64], a2);
            a3 = fmaf(av[k + 3], hp[(size_t)(mb + k + 3) * 64], a3);
        }
        part[tid] = (a0 + a1) + (a2 + a3);
    }
    __syncthreads();
    if (tid < 128) {
        int r = tid >> 6, o = tid & 63;
        float x = (part[r * 256 + o] + part[r * 256 + 64 + o] +
                   part[r * 256 + 128 + o] + part[r * 256 + 192 + o]) * inv[r] + b2[o];
        xrow[tid] = x > 0.f ? x : expm1f(x);
    }
    __syncthreads();
    if (tid < 64) {
        float vv = xrow[tid] * xrow[64 + tid];
        vsm[tid] = vv;
        out_vsm[b * 64 + tid] = vv;
    }
    __syncthreads();
    if (tid < 192) {
        float acc = fc1_b[tid];
        for (int f = 0; f < 64; f++) acc = fmaf(vsm[f], fc1_w[f * 192 + tid], acc);
        v1[tid] = fmaxf(acc, 0.f);
    }
    __syncthreads();
    if (tid < 64) {
        float acc = fc2_b[tid];
        for (int f = 0; f < 192; f++) acc = fmaf(v1[f], fc2_w[f * 64 + tid], acc);
        v2s[tid] = fmaxf(acc, 0.f);
    }
    __syncthreads();
    if (tid < 2) {
        float acc = fc3_b[tid];
        for (int f = 0; f < 64; f++) acc = fmaf(v2s[f], fc3_w[f * 2 + tid], acc);
        sc[tid] = acc;
    }
    __syncthreads();
    if (tid < 2) {
        float m = fmaxf(sc[0], sc[1]);
        float lse = m + logf(expf(sc[0] - m) + expf(sc[1] - m));
        out_scores[b * 2 + tid] = sc[tid] - lse;
    }
}

// ---------------- launch ----------------
extern "C" void kernel_launch(void* const* d_in, const int* in_sizes, int n_in,
                              void* d_out, int out_size) {
    (void)in_sizes; (void)n_in; (void)out_size;
    const float* features = (const float*)d_in[0];
    const int*   adj      = (const int*)  d_in[1];
    const float* line_emb = (const float*)d_in[5];
    const int*   v_types  = (const int*)  d_in[6];
    const float* w1       = (const float*)d_in[7];
    const float* a_src1   = (const float*)d_in[8];
    const float* a_dst1   = (const float*)d_in[9];
    const float* b1       = (const float*)d_in[10];
    const float* w2       = (const float*)d_in[11];
    const float* a_src2   = (const float*)d_in[12];
    const float* a_dst2   = (const float*)d_in[13];
    const float* b2       = (const float*)d_in[14];
    const float* fc1_w    = (const float*)d_in[15];
    const float* fc1_b    = (const float*)d_in[16];
    const float* fc2_w    = (const float*)d_in[17];
    const float* fc2_b    = (const float*)d_in[18];
    const float* fc3_w    = (const float*)d_in[19];
    const float* fc3_b    = (const float*)d_in[20];

    float* out   = (float*)d_out;
    float* vsm   = out + 64;       // v_sim_mul [32,64]
    float* attn1 = out + 2112;     // attn1 [32,8,512,512]

    cudaFuncSetAttribute(k_proj1, cudaFuncAttributeMaxDynamicSharedMemorySize, 67000);
    cudaFuncSetAttribute(k_gemm,  cudaFuncAttributeMaxDynamicSharedMemorySize, 74000);

    k_pack <<<32768, 256>>>(adj);
    k_proj1<<<dim3(8, 2, 32), 512, 66304>>>(features, line_emb, v_types, w1, a_src1, a_dst1);
    k_store<<<dim3(2, 8, 32), 256>>>(attn1);
    k_gemm <<<dim3(8, 32), 256, 73792>>>(b1);
    k_proj2<<<dim3(16, 32), 256>>>(v_types, w2, a_src2, a_dst2);
    k_final<<<32, 512>>>(b2, fc1_w, fc1_b, fc2_w, fc2_b, fc3_w, fc3_b, out, vsm);
}